// round 14
// baseline (speedup 1.0000x reference)
#include <cuda_runtime.h>
#include <math.h>

// Problem constants
// B=256, LAT=20, HID=128, G=25000, BIN=25, C=7, GB=1000
// Output layout (concatenated f32):
//   mu      [256,25000]      @ 0
//   theta   [256,25000]      @ 6,400,000
//   pi_drop [256,25000]      @ 12,800,000
//   sample  [256,25000]      @ 19,200,000
//   pi      [256,25000,7]    @ 25,600,000   (total 70,400,000)

static __device__ float g_x2[256 * 128];      // [b][k] for rho gemm
static __device__ float g_x2t[128 * 256];     // [k][b] for big gemm tiles
static __device__ float g_logits[256 * 7000]; // rho logits [b][c*1000+o]

// Side stream + events (created pre-capture; context resources, not device mem).
namespace {
struct HxStreams {
    cudaStream_t s1 = nullptr;
    cudaEvent_t e0 = nullptr, e1 = nullptr;
    HxStreams() {
        cudaStreamCreateWithFlags(&s1, cudaStreamNonBlocking);
        cudaEventCreateWithFlags(&e0, cudaEventDisableTiming);
        cudaEventCreateWithFlags(&e1, cudaEventDisableTiming);
    }
};
HxStreams g_sx;
}

// ---------------------------------------------------------------------------
// packed f32x2 helpers
// ---------------------------------------------------------------------------
__device__ __forceinline__ unsigned long long packf2(float lo, float hi) {
    unsigned long long r;
    asm("mov.b64 %0, {%1, %2};" : "=l"(r) : "f"(lo), "f"(hi));
    return r;
}
__device__ __forceinline__ float2 unpackf2(unsigned long long v) {
    float lo, hi;
    asm("mov.b64 {%0, %1}, %2;" : "=f"(lo), "=f"(hi) : "l"(v));
    return make_float2(lo, hi);
}
__device__ __forceinline__ void ffma2(unsigned long long& d, unsigned long long a,
                                      unsigned long long b) {
    asm("fma.rn.f32x2 %0, %1, %2, %0;" : "+l"(d) : "l"(a), "l"(b));
}

// ---------------------------------------------------------------------------
// Threefry-2x32, 20 rounds, key = (0, 42), partitionable mode
// ---------------------------------------------------------------------------
__device__ __forceinline__ void tf2x32(unsigned x0, unsigned x1,
                                       unsigned& o0, unsigned& o1) {
    const unsigned K0 = 0u;
    const unsigned K1 = 42u;
    const unsigned K2 = 0x1BD11BDAu ^ 0u ^ 42u;
    x0 += K0; x1 += K1;
#define TF_R(r) { x0 += x1; x1 = __funnelshift_l(x1, x1, r); x1 ^= x0; }
    TF_R(13) TF_R(15) TF_R(26) TF_R(6)
    x0 += K1; x1 += K2 + 1u;
    TF_R(17) TF_R(29) TF_R(16) TF_R(24)
    x0 += K2; x1 += K0 + 2u;
    TF_R(13) TF_R(15) TF_R(26) TF_R(6)
    x0 += K0; x1 += K1 + 3u;
    TF_R(17) TF_R(29) TF_R(16) TF_R(24)
    x0 += K1; x1 += K2 + 4u;
    TF_R(13) TF_R(15) TF_R(26) TF_R(6)
    x0 += K2; x1 += K0 + 5u;
#undef TF_R
    o0 = x0; o1 = x1;
}

__device__ __forceinline__ float bits_to_uniform(unsigned bits) {
    return __uint_as_float((bits >> 9) | 0x3f800000u) - 1.0f;
}

// ---------------------------------------------------------------------------
// Fused MLP: x2 = relu(bn(relu(bn(z@w0+b0)) @ w1 + b1)); writes both layouts
// ---------------------------------------------------------------------------
__global__ void mlp_kernel(const float* __restrict__ z,
                           const float* __restrict__ w0, const float* __restrict__ b0,
                           const float* __restrict__ g0, const float* __restrict__ be0,
                           const float* __restrict__ m0, const float* __restrict__ v0,
                           const float* __restrict__ w1, const float* __restrict__ b1,
                           const float* __restrict__ g1, const float* __restrict__ be1,
                           const float* __restrict__ m1, const float* __restrict__ v1) {
    __shared__ float zr[20];
    __shared__ float xr[128];
    int b = blockIdx.x, h = threadIdx.x;
    if (h < 20) zr[h] = z[b * 20 + h];
    __syncthreads();
    float acc = b0[h];
#pragma unroll
    for (int k = 0; k < 20; k++) acc = fmaf(zr[k], w0[k * 128 + h], acc);
    acc = (acc - m0[h]) * rsqrtf(v0[h] + 1e-3f) * g0[h] + be0[h];
    xr[h] = fmaxf(acc, 0.f);
    __syncthreads();
    float a0 = b1[h], a1 = 0.f, a2 = 0.f, a3 = 0.f;
#pragma unroll 8
    for (int k = 0; k < 128; k += 4) {
        a0 = fmaf(xr[k], w1[k * 128 + h], a0);
        a1 = fmaf(xr[k + 1], w1[(k + 1) * 128 + h], a1);
        a2 = fmaf(xr[k + 2], w1[(k + 2) * 128 + h], a2);
        a3 = fmaf(xr[k + 3], w1[(k + 3) * 128 + h], a3);
    }
    float acc2 = (a0 + a1) + (a2 + a3);
    acc2 = (acc2 - m1[h]) * rsqrtf(v1[h] + 1e-3f) * g1[h] + be1[h];
    float r = fmaxf(acc2, 0.f);
    g_x2[b * 128 + h] = r;
    g_x2t[h * 256 + b] = r;
}

// ---------------------------------------------------------------------------
// rho GEMM: logits[b][j] = x2[b] . wrho[c,:,o] + brho[c,o],  j = c*1000+o
// ---------------------------------------------------------------------------
__global__ void __launch_bounds__(256, 4)
rho_gemm_kernel(const float* __restrict__ wrho, const float* __restrict__ brho) {
    __shared__ unsigned long long xsp[128 * 8];
    int tid = threadIdx.x;
    int b0r = blockIdx.y * 16;
    for (int i = tid; i < 128 * 8; i += 256) {
        int k = i >> 3, i2 = i & 7;
        float lo = g_x2[(b0r + 2 * i2) * 128 + k];
        float hi = g_x2[(b0r + 2 * i2 + 1) * 128 + k];
        xsp[i] = packf2(lo, hi);
    }
    __syncthreads();
    int j = blockIdx.x * 256 + tid;
    if (j >= 7000) return;
    int c = j / 1000;
    int o = j - c * 1000;
    const float* wb = wrho + c * 128000 + o;
    unsigned long long acc[8];
    {
        float bv = brho[c * 1000 + o];
        unsigned long long b2 = packf2(bv, bv);
#pragma unroll
        for (int i = 0; i < 8; i++) acc[i] = b2;
    }
#pragma unroll 4
    for (int k = 0; k < 128; k++) {
        float wv = wb[k * 1000];
        unsigned long long w2 = packf2(wv, wv);
#pragma unroll
        for (int i = 0; i < 8; i++) ffma2(acc[i], xsp[k * 8 + i], w2);
    }
#pragma unroll
    for (int i = 0; i < 8; i++) {
        float2 t = unpackf2(acc[i]);
        g_logits[(b0r + 2 * i) * 7000 + j] = t.x;
        g_logits[(b0r + 2 * i + 1) * 7000 + j] = t.y;
    }
}

// ---------------------------------------------------------------------------
// Tiled theta / pi_drop GEMM.  C-tile 128b x 128g per block; k-chunks of 16
// staged in smem. Weights are read from L2/DRAM only ONCE per b-tile
// (51 MB total vs 819 MB in the per-thread-column version) -> fma-bound.
// Thread = (ty,tx) computes 8b x 8g via 32 u64 FFMA2 accumulators:
//   acc[bb][gp] = (out[b][g], out[b][g+1]);  x staged duplicated (x,x),
//   w pairs natural from f32 smem row.
// grid (196, 2, 2): gx, b-tile, which (0=theta exp, 1=pi_drop).
// ---------------------------------------------------------------------------
__global__ void __launch_bounds__(256, 2)
big_gemm_kernel(const float* __restrict__ wr, const float* __restrict__ br,
                const float* __restrict__ wd, const float* __restrict__ bd,
                float* __restrict__ out) {
    __shared__ unsigned long long xdup[16 * 128];  // [k][b] = (x,x)  16KB
    __shared__ float ws[16 * 128];                 // [k][g]          8KB
    int tid = threadIdx.x;
    int tx = tid & 15, ty = tid >> 4;
    int g0 = blockIdx.x * 128;
    int b0 = blockIdx.y * 128;
    int which = blockIdx.z;
    const float* wsel = which ? wd : wr;
    const float* bsel = which ? bd : br;

    bool valid = (g0 + tx * 8) < 25000;   // 25000-24960=40, divisible by 8
    int gsafe = valid ? (g0 + tx * 8) : 0;

    unsigned long long acc[8][4];
    {
        const ulonglong2* bb2 = (const ulonglong2*)(bsel + gsafe);
        ulonglong2 p0 = bb2[0], p1 = bb2[1];
#pragma unroll
        for (int bb = 0; bb < 8; bb++) {
            acc[bb][0] = p0.x; acc[bb][1] = p0.y;
            acc[bb][2] = p1.x; acc[bb][3] = p1.y;
        }
    }

    for (int kc = 0; kc < 8; kc++) {
        __syncthreads();
        for (int s = tid; s < 2048; s += 256) {
            int k = s >> 7, bl = s & 127;
            float xv = g_x2t[(kc * 16 + k) * 256 + b0 + bl];
            xdup[s] = packf2(xv, xv);
        }
        for (int s = tid; s < 2048; s += 256) {
            int k = s >> 7, gl = s & 127;
            int g = g0 + gl;
            if (g >= 25000) g = 24999;
            ws[s] = wsel[(size_t)(kc * 16 + k) * 25000 + g];
        }
        __syncthreads();
#pragma unroll
        for (int k = 0; k < 16; k++) {
            const ulonglong2* xp = (const ulonglong2*)&xdup[k * 128 + ty * 8];
            ulonglong2 x01 = xp[0], x23 = xp[1], x45 = xp[2], x67 = xp[3];
            const ulonglong2* wp = (const ulonglong2*)&ws[k * 128 + tx * 8];
            ulonglong2 wa = wp[0], wb = wp[1];
            unsigned long long xv[8] = {x01.x, x01.y, x23.x, x23.y,
                                        x45.x, x45.y, x67.x, x67.y};
            unsigned long long wv[4] = {wa.x, wa.y, wb.x, wb.y};
#pragma unroll
            for (int bb = 0; bb < 8; bb++) {
#pragma unroll
                for (int gp = 0; gp < 4; gp++) {
                    ffma2(acc[bb][gp], xv[bb], wv[gp]);
                }
            }
        }
    }

    if (valid) {
        if (which == 0) {
#pragma unroll
            for (int bb = 0; bb < 8; bb++) {
                float* dst = &out[6400000 + (size_t)(b0 + ty * 8 + bb) * 25000 + g0 + tx * 8];
                float2 p0 = unpackf2(acc[bb][0]);
                float2 p1 = unpackf2(acc[bb][1]);
                float2 p2 = unpackf2(acc[bb][2]);
                float2 p3 = unpackf2(acc[bb][3]);
                ((float4*)dst)[0] = make_float4(__expf(p0.x), __expf(p0.y),
                                                __expf(p1.x), __expf(p1.y));
                ((float4*)dst)[1] = make_float4(__expf(p2.x), __expf(p2.y),
                                                __expf(p3.x), __expf(p3.y));
            }
        } else {
#pragma unroll
            for (int bb = 0; bb < 8; bb++) {
                float* dst = &out[12800000 + (size_t)(b0 + ty * 8 + bb) * 25000 + g0 + tx * 8];
                ulonglong2 o0, o1;
                o0.x = acc[bb][0]; o0.y = acc[bb][1];
                o1.x = acc[bb][2]; o1.y = acc[bb][3];
                ((ulonglong2*)dst)[0] = o0;
                ((ulonglong2*)dst)[1] = o1;
            }
        }
    }
}

// ---------------------------------------------------------------------------
// Sample kernel: inline rho-softmax + threefry gumbel argmax.
// Fast path __logf; exact logf fallback when winner margin < 1e-4.
// ---------------------------------------------------------------------------
__global__ void __launch_bounds__(256)
sample_kernel(const float* __restrict__ ws, const float* __restrict__ bs,
              float* __restrict__ out) {
    __shared__ float sp[12 * 7];
    __shared__ float spo[256 * 7];
    int tid = threadIdx.x;
    int g0 = blockIdx.x * 256;
    int b = blockIdx.y;                  // 0..255
    int nvalid = min(256, 25000 - g0);
    int bin0 = g0 / 25;
    int nbins = (g0 + nvalid - 1) / 25 - bin0 + 1;  // <= 11
    int npl = nbins * 7;
    for (int i = tid; i < npl; i += 256) {
        int bl = i / 7, c = i - bl * 7;
        sp[i] = g_logits[b * 7000 + c * 1000 + bin0 + bl];
    }
    __syncthreads();
    if (tid < nbins) {
        float v[7];
        float mx = -1e30f;
#pragma unroll
        for (int c = 0; c < 7; c++) { v[c] = sp[tid * 7 + c]; mx = fmaxf(mx, v[c]); }
        float s = 0.f;
#pragma unroll
        for (int c = 0; c < 7; c++) { v[c] = expf(v[c] - mx); s += v[c]; }
        float inv = 1.f / s;
#pragma unroll
        for (int c = 0; c < 7; c++) sp[tid * 7 + c] = v[c] * inv;
    }
    __syncthreads();
    if (tid < nvalid) {
        int g = g0 + tid;
        int binl = g / 25 - bin0;
        const float* p = &sp[binl * 7];
        unsigned base = (unsigned)(b * 25000 + g) * 7u;
        float a[7], w[7];
#pragma unroll
        for (int c = 0; c < 7; c++) {
            unsigned o0, o1;
            tf2x32(0u, base + (unsigned)c, o0, o1);
            float u = bits_to_uniform(o0 ^ o1);
            w[c] = 1e-20f - __logf(u + 1e-20f);   // > 0, fast log
            float pc = p[c];
            spo[tid * 7 + c] = pc;
            a[c] = pc + 1e-20f;                    // > 0
        }
        int bb = 0;
#pragma unroll
        for (int c = 1; c < 7; c++) {
            if (a[c] * w[bb] > a[bb] * w[c]) bb = c;
        }
        float abb = a[bb], wbb = w[bb];
        bool close = false;
#pragma unroll
        for (int c = 0; c < 7; c++) {
            if (c != bb) close |= !(abb * w[c] > a[c] * wbb * (1.0f + 1e-4f));
        }
        float s;
        if (!close) {
            s = (float)bb;
        } else {
            float we[7];
#pragma unroll
            for (int c = 0; c < 7; c++) {
                unsigned o0, o1;
                tf2x32(0u, base + (unsigned)c, o0, o1);
                float u = bits_to_uniform(o0 ^ o1);
                we[c] = 1e-20f - logf(u + 1e-20f);
            }
            int be = 0;
#pragma unroll
            for (int c = 1; c < 7; c++) {
                if (a[c] * we[be] > a[be] * we[c]) be = c;
            }
            float abe = a[be], wbe = we[be];
            s = 0.f;
#pragma unroll
            for (int c = 0; c < 7; c++) {
                if (a[c] * wbe == abe * we[c]) s += (float)c;
            }
        }
        float wsg = ws[g], bsg = bs[g];
        out[b * 25000 + g] = 1.f / (1.f + __expf(-(s * wsg + bsg)));
        out[19200000 + b * 25000 + g] = s;
    }
    __syncthreads();
    int tot4 = (nvalid * 7) >> 2;       // nvalid*7 divisible by 4 (256 or 168)
    float4* pib4 = (float4*)(out + 25600000u + (unsigned)(b * 25000 + g0) * 7u);
    const float4* spo4 = (const float4*)spo;
    for (int i = tid; i < tot4; i += 256) {
        pib4[i] = spo4[i];
    }
}

// ---------------------------------------------------------------------------
extern "C" void kernel_launch(void* const* d_in, const int* in_sizes, int n_in,
                              void* d_out, int out_size) {
    const float* z    = (const float*)d_in[0];
    const float* w0   = (const float*)d_in[1];
    const float* b0   = (const float*)d_in[2];
    const float* g0   = (const float*)d_in[3];
    const float* be0  = (const float*)d_in[4];
    const float* m0   = (const float*)d_in[5];
    const float* v0   = (const float*)d_in[6];
    const float* w1   = (const float*)d_in[7];
    const float* b1   = (const float*)d_in[8];
    const float* g1   = (const float*)d_in[9];
    const float* be1  = (const float*)d_in[10];
    const float* m1   = (const float*)d_in[11];
    const float* v1   = (const float*)d_in[12];
    const float* wr   = (const float*)d_in[13];
    const float* br   = (const float*)d_in[14];
    const float* wd   = (const float*)d_in[15];
    const float* bd   = (const float*)d_in[16];
    const float* wrho = (const float*)d_in[17];
    const float* brho = (const float*)d_in[18];
    const float* wsc  = (const float*)d_in[19];
    const float* bsc  = (const float*)d_in[20];
    float* out = (float*)d_out;

    // main stream: mlp -> rho_gemm -> sample ; side stream: tiled big_gemm
    mlp_kernel<<<256, 128>>>(z, w0, b0, g0, be0, m0, v0, w1, b1, g1, be1, m1, v1);
    cudaEventRecord(g_sx.e0, 0);
    cudaStreamWaitEvent(g_sx.s1, g_sx.e0, 0);
    big_gemm_kernel<<<dim3(196, 2, 2), 256, 0, g_sx.s1>>>(wr, br, wd, bd, out);
    rho_gemm_kernel<<<dim3(28, 16), 256>>>(wrho, brho);
    sample_kernel<<<dim3(98, 256), 256>>>(wsc, bsc, out);
    cudaEventRecord(g_sx.e1, g_sx.s1);
    cudaStreamWaitEvent(0, g_sx.e1, 0);
}

// round 17
// speedup vs baseline: 1.1016x; 1.1016x over previous
#include <cuda_runtime.h>
#include <math.h>

// Problem constants
// B=256, LAT=20, HID=128, G=25000, BIN=25, C=7, GB=1000
// Output layout (concatenated f32):
//   mu      [256,25000]      @ 0
//   theta   [256,25000]      @ 6,400,000
//   pi_drop [256,25000]      @ 12,800,000
//   sample  [256,25000]      @ 19,200,000
//   pi      [256,25000,7]    @ 25,600,000   (total 70,400,000)

static __device__ float g_x2[256 * 128];      // [b][k] for rho gemm
static __device__ float g_x2t[128 * 256];     // [k][b] for big gemm tiles
static __device__ float g_logits[256 * 7000]; // rho logits [b][c*1000+o]

// Side stream + events (created pre-capture; context resources, not device mem).
namespace {
struct HxStreams {
    cudaStream_t s1 = nullptr;
    cudaEvent_t e0 = nullptr, e1 = nullptr;
    HxStreams() {
        cudaStreamCreateWithFlags(&s1, cudaStreamNonBlocking);
        cudaEventCreateWithFlags(&e0, cudaEventDisableTiming);
        cudaEventCreateWithFlags(&e1, cudaEventDisableTiming);
    }
};
HxStreams g_sx;
}

// ---------------------------------------------------------------------------
// packed f32x2 helpers
// ---------------------------------------------------------------------------
__device__ __forceinline__ unsigned long long packf2(float lo, float hi) {
    unsigned long long r;
    asm("mov.b64 %0, {%1, %2};" : "=l"(r) : "f"(lo), "f"(hi));
    return r;
}
__device__ __forceinline__ float2 unpackf2(unsigned long long v) {
    float lo, hi;
    asm("mov.b64 {%0, %1}, %2;" : "=f"(lo), "=f"(hi) : "l"(v));
    return make_float2(lo, hi);
}
__device__ __forceinline__ void ffma2(unsigned long long& d, unsigned long long a,
                                      unsigned long long b) {
    asm("fma.rn.f32x2 %0, %1, %2, %0;" : "+l"(d) : "l"(a), "l"(b));
}

// ---------------------------------------------------------------------------
// Threefry-2x32, 20 rounds, key = (0, 42), partitionable mode
// ---------------------------------------------------------------------------
__device__ __forceinline__ void tf2x32(unsigned x0, unsigned x1,
                                       unsigned& o0, unsigned& o1) {
    const unsigned K0 = 0u;
    const unsigned K1 = 42u;
    const unsigned K2 = 0x1BD11BDAu ^ 0u ^ 42u;
    x0 += K0; x1 += K1;
#define TF_R(r) { x0 += x1; x1 = __funnelshift_l(x1, x1, r); x1 ^= x0; }
    TF_R(13) TF_R(15) TF_R(26) TF_R(6)
    x0 += K1; x1 += K2 + 1u;
    TF_R(17) TF_R(29) TF_R(16) TF_R(24)
    x0 += K2; x1 += K0 + 2u;
    TF_R(13) TF_R(15) TF_R(26) TF_R(6)
    x0 += K0; x1 += K1 + 3u;
    TF_R(17) TF_R(29) TF_R(16) TF_R(24)
    x0 += K1; x1 += K2 + 4u;
    TF_R(13) TF_R(15) TF_R(26) TF_R(6)
    x0 += K2; x1 += K0 + 5u;
#undef TF_R
    o0 = x0; o1 = x1;
}

__device__ __forceinline__ float bits_to_uniform(unsigned bits) {
    return __uint_as_float((bits >> 9) | 0x3f800000u) - 1.0f;
}

// ---------------------------------------------------------------------------
// Fused MLP: x2 = relu(bn(relu(bn(z@w0+b0)) @ w1 + b1)); writes both layouts
// ---------------------------------------------------------------------------
__global__ void mlp_kernel(const float* __restrict__ z,
                           const float* __restrict__ w0, const float* __restrict__ b0,
                           const float* __restrict__ g0, const float* __restrict__ be0,
                           const float* __restrict__ m0, const float* __restrict__ v0,
                           const float* __restrict__ w1, const float* __restrict__ b1,
                           const float* __restrict__ g1, const float* __restrict__ be1,
                           const float* __restrict__ m1, const float* __restrict__ v1) {
    __shared__ float zr[20];
    __shared__ float xr[128];
    int b = blockIdx.x, h = threadIdx.x;
    if (h < 20) zr[h] = z[b * 20 + h];
    __syncthreads();
    float acc = b0[h];
#pragma unroll
    for (int k = 0; k < 20; k++) acc = fmaf(zr[k], w0[k * 128 + h], acc);
    acc = (acc - m0[h]) * rsqrtf(v0[h] + 1e-3f) * g0[h] + be0[h];
    xr[h] = fmaxf(acc, 0.f);
    __syncthreads();
    float a0 = b1[h], a1 = 0.f, a2 = 0.f, a3 = 0.f;
#pragma unroll 8
    for (int k = 0; k < 128; k += 4) {
        a0 = fmaf(xr[k], w1[k * 128 + h], a0);
        a1 = fmaf(xr[k + 1], w1[(k + 1) * 128 + h], a1);
        a2 = fmaf(xr[k + 2], w1[(k + 2) * 128 + h], a2);
        a3 = fmaf(xr[k + 3], w1[(k + 3) * 128 + h], a3);
    }
    float acc2 = (a0 + a1) + (a2 + a3);
    acc2 = (acc2 - m1[h]) * rsqrtf(v1[h] + 1e-3f) * g1[h] + be1[h];
    float r = fmaxf(acc2, 0.f);
    g_x2[b * 128 + h] = r;
    g_x2t[h * 256 + b] = r;
}

// ---------------------------------------------------------------------------
// rho GEMM: logits[b][j] = x2[b] . wrho[c,:,o] + brho[c,o],  j = c*1000+o
// ---------------------------------------------------------------------------
__global__ void __launch_bounds__(256, 4)
rho_gemm_kernel(const float* __restrict__ wrho, const float* __restrict__ brho) {
    __shared__ unsigned long long xsp[128 * 8];
    int tid = threadIdx.x;
    int b0r = blockIdx.y * 16;
    for (int i = tid; i < 128 * 8; i += 256) {
        int k = i >> 3, i2 = i & 7;
        float lo = g_x2[(b0r + 2 * i2) * 128 + k];
        float hi = g_x2[(b0r + 2 * i2 + 1) * 128 + k];
        xsp[i] = packf2(lo, hi);
    }
    __syncthreads();
    int j = blockIdx.x * 256 + tid;
    if (j >= 7000) return;
    int c = j / 1000;
    int o = j - c * 1000;
    const float* wb = wrho + c * 128000 + o;
    unsigned long long acc[8];
    {
        float bv = brho[c * 1000 + o];
        unsigned long long b2 = packf2(bv, bv);
#pragma unroll
        for (int i = 0; i < 8; i++) acc[i] = b2;
    }
#pragma unroll 4
    for (int k = 0; k < 128; k++) {
        float wv = wb[k * 1000];
        unsigned long long w2 = packf2(wv, wv);
#pragma unroll
        for (int i = 0; i < 8; i++) ffma2(acc[i], xsp[k * 8 + i], w2);
    }
#pragma unroll
    for (int i = 0; i < 8; i++) {
        float2 t = unpackf2(acc[i]);
        g_logits[(b0r + 2 * i) * 7000 + j] = t.x;
        g_logits[(b0r + 2 * i + 1) * 7000 + j] = t.y;
    }
}

// ---------------------------------------------------------------------------
// Tiled theta / pi_drop GEMM v2 — balanced L2 / LDS-crossbar / fma.
// Block tile 128b x 256g; thread (ty,tx) = 8b x 16g (16g spread as 4 float4
// chunks at +0/64/128/192 to avoid smem bank conflicts). k-chunks of 8,
// DOUBLE-BUFFERED (prefetch->regs, compute, STS, sync).
//   per k per thread: 4 LDS.128 (x-dup) + 4 LDS.128 (w) + 128 FMA (64 FFMA2)
//   => 1.0 B_smem/FMA; chip: LDS ~45us on crossbar, FFMA2 ~45us on fma pipe.
// Weights read from L2 once per b-tile (51 MB total).
// grid (98, 2, 2): g-tile, b-tile, which (0=theta exp, 1=pi_drop). occ 1.
// ---------------------------------------------------------------------------
__global__ void __launch_bounds__(256)
big_gemm_kernel(const float* __restrict__ wr, const float* __restrict__ br,
                const float* __restrict__ wd, const float* __restrict__ bd,
                float* __restrict__ out) {
    __shared__ unsigned long long xdup[2][8 * 128];  // [buf][k][b] = (x,x) 16KB
    __shared__ float wsm[2][8 * 256];                // [buf][k][g]       8KB
    int tid = threadIdx.x;
    int tx = tid & 15, ty = tid >> 4;
    int g0 = blockIdx.x * 256;
    int b0 = blockIdx.y * 128;
    const float* wsel = blockIdx.z ? wd : wr;
    const float* bsel = blockIdx.z ? bd : br;

    int fxk = tid >> 5, fxb = tid & 31;   // x-fill: k row, b quad

    // prologue: fill buffer 0 (kc = 0)
    {
        float4 xv = *(const float4*)&g_x2t[(0 * 8 + fxk) * 256 + b0 + fxb * 4];
        ulonglong2* xd = (ulonglong2*)&xdup[0][fxk * 128 + fxb * 4];
        ulonglong2 t0, t1;
        t0.x = packf2(xv.x, xv.x); t0.y = packf2(xv.y, xv.y);
        t1.x = packf2(xv.z, xv.z); t1.y = packf2(xv.w, xv.w);
        xd[0] = t0; xd[1] = t1;
#pragma unroll
        for (int i = 0; i < 2; i++) {
            int idx = tid + i * 256;
            int k = idx >> 6, gq = idx & 63;
            int g = min(g0 + gq * 4, 24996);
            float4 wv = *(const float4*)&wsel[(size_t)k * 25000 + g];
            *(float4*)&wsm[0][k * 256 + gq * 4] = wv;
        }
    }
    __syncthreads();

    unsigned long long acc[8][4][2];   // [bb][j][pair] = 64 u64
    {
#pragma unroll
        for (int j = 0; j < 4; j++) {
            int g = min(g0 + j * 64 + tx * 4, 24996);
            ulonglong2 bv = *(const ulonglong2*)(bsel + g);
#pragma unroll
            for (int bb = 0; bb < 8; bb++) {
                acc[bb][j][0] = bv.x;
                acc[bb][j][1] = bv.y;
            }
        }
    }

    for (int kc = 0; kc < 16; kc++) {
        int cur = kc & 1;
        float4 px;
        float4 pw0, pw1;
        if (kc < 15) {
            px = *(const float4*)&g_x2t[((kc + 1) * 8 + fxk) * 256 + b0 + fxb * 4];
            {
                int k = tid >> 6, gq = tid & 63;
                int g = min(g0 + gq * 4, 24996);
                pw0 = *(const float4*)&wsel[(size_t)((kc + 1) * 8 + k) * 25000 + g];
            }
            {
                int idx = tid + 256;
                int k = idx >> 6, gq = idx & 63;
                int g = min(g0 + gq * 4, 24996);
                pw1 = *(const float4*)&wsel[(size_t)((kc + 1) * 8 + k) * 25000 + g];
            }
        }
#pragma unroll
        for (int k = 0; k < 8; k++) {
            const ulonglong2* xp = (const ulonglong2*)&xdup[cur][k * 128 + ty * 8];
            ulonglong2 xa = xp[0], xb = xp[1], xc = xp[2], xdd = xp[3];
            unsigned long long xv[8] = {xa.x, xa.y, xb.x, xb.y,
                                        xc.x, xc.y, xdd.x, xdd.y};
            unsigned long long wv[4][2];
#pragma unroll
            for (int j = 0; j < 4; j++) {
                ulonglong2 wp = *(const ulonglong2*)&wsm[cur][k * 256 + j * 64 + tx * 4];
                wv[j][0] = wp.x; wv[j][1] = wp.y;
            }
#pragma unroll
            for (int bb = 0; bb < 8; bb++) {
#pragma unroll
                for (int j = 0; j < 4; j++) {
                    ffma2(acc[bb][j][0], xv[bb], wv[j][0]);
                    ffma2(acc[bb][j][1], xv[bb], wv[j][1]);
                }
            }
        }
        if (kc < 15) {
            int nb = 1 - cur;
            ulonglong2* xd = (ulonglong2*)&xdup[nb][fxk * 128 + fxb * 4];
            ulonglong2 t0, t1;
            t0.x = packf2(px.x, px.x); t0.y = packf2(px.y, px.y);
            t1.x = packf2(px.z, px.z); t1.y = packf2(px.w, px.w);
            xd[0] = t0; xd[1] = t1;
            {
                int k = tid >> 6, gq = tid & 63;
                *(float4*)&wsm[nb][k * 256 + gq * 4] = pw0;
            }
            {
                int idx = tid + 256;
                int k = idx >> 6, gq = idx & 63;
                *(float4*)&wsm[nb][k * 256 + gq * 4] = pw1;
            }
        }
        __syncthreads();
    }

    // store: 8 rows x 4 float4 chunks, masked for the partial last g-tile
    if (blockIdx.z == 0) {
#pragma unroll
        for (int bb = 0; bb < 8; bb++) {
            size_t row = (size_t)(b0 + ty * 8 + bb) * 25000;
#pragma unroll
            for (int j = 0; j < 4; j++) {
                int g = g0 + j * 64 + tx * 4;
                if (g + 3 < 25000) {
                    float2 p0 = unpackf2(acc[bb][j][0]);
                    float2 p1 = unpackf2(acc[bb][j][1]);
                    *(float4*)&out[6400000 + row + g] =
                        make_float4(__expf(p0.x), __expf(p0.y),
                                    __expf(p1.x), __expf(p1.y));
                }
            }
        }
    } else {
#pragma unroll
        for (int bb = 0; bb < 8; bb++) {
            size_t row = (size_t)(b0 + ty * 8 + bb) * 25000;
#pragma unroll
            for (int j = 0; j < 4; j++) {
                int g = g0 + j * 64 + tx * 4;
                if (g + 3 < 25000) {
                    ulonglong2 o2;
                    o2.x = acc[bb][j][0]; o2.y = acc[bb][j][1];
                    *(ulonglong2*)&out[12800000 + row + g] = o2;
                }
            }
        }
    }
}

// ---------------------------------------------------------------------------
// Sample kernel: inline rho-softmax + threefry gumbel argmax.
// Fast path __logf; exact logf fallback when winner margin < 1e-4.
// ---------------------------------------------------------------------------
__global__ void __launch_bounds__(256)
sample_kernel(const float* __restrict__ ws, const float* __restrict__ bs,
              float* __restrict__ out) {
    __shared__ float sp[12 * 7];
    __shared__ float spo[256 * 7];
    int tid = threadIdx.x;
    int g0 = blockIdx.x * 256;
    int b = blockIdx.y;                  // 0..255
    int nvalid = min(256, 25000 - g0);
    int bin0 = g0 / 25;
    int nbins = (g0 + nvalid - 1) / 25 - bin0 + 1;  // <= 11
    int npl = nbins * 7;
    for (int i = tid; i < npl; i += 256) {
        int bl = i / 7, c = i - bl * 7;
        sp[i] = g_logits[b * 7000 + c * 1000 + bin0 + bl];
    }
    __syncthreads();
    if (tid < nbins) {
        float v[7];
        float mx = -1e30f;
#pragma unroll
        for (int c = 0; c < 7; c++) { v[c] = sp[tid * 7 + c]; mx = fmaxf(mx, v[c]); }
        float s = 0.f;
#pragma unroll
        for (int c = 0; c < 7; c++) { v[c] = expf(v[c] - mx); s += v[c]; }
        float inv = 1.f / s;
#pragma unroll
        for (int c = 0; c < 7; c++) sp[tid * 7 + c] = v[c] * inv;
    }
    __syncthreads();
    if (tid < nvalid) {
        int g = g0 + tid;
        int binl = g / 25 - bin0;
        const float* p = &sp[binl * 7];
        unsigned base = (unsigned)(b * 25000 + g) * 7u;
        float a[7], w[7];
#pragma unroll
        for (int c = 0; c < 7; c++) {
            unsigned o0, o1;
            tf2x32(0u, base + (unsigned)c, o0, o1);
            float u = bits_to_uniform(o0 ^ o1);
            w[c] = 1e-20f - __logf(u + 1e-20f);   // > 0, fast log
            float pc = p[c];
            spo[tid * 7 + c] = pc;
            a[c] = pc + 1e-20f;                    // > 0
        }
        int bb = 0;
#pragma unroll
        for (int c = 1; c < 7; c++) {
            if (a[c] * w[bb] > a[bb] * w[c]) bb = c;
        }
        float abb = a[bb], wbb = w[bb];
        bool close = false;
#pragma unroll
        for (int c = 0; c < 7; c++) {
            if (c != bb) close |= !(abb * w[c] > a[c] * wbb * (1.0f + 1e-4f));
        }
        float s;
        if (!close) {
            s = (float)bb;
        } else {
            float we[7];
#pragma unroll
            for (int c = 0; c < 7; c++) {
                unsigned o0, o1;
                tf2x32(0u, base + (unsigned)c, o0, o1);
                float u = bits_to_uniform(o0 ^ o1);
                we[c] = 1e-20f - logf(u + 1e-20f);
            }
            int be = 0;
#pragma unroll
            for (int c = 1; c < 7; c++) {
                if (a[c] * we[be] > a[be] * we[c]) be = c;
            }
            float abe = a[be], wbe = we[be];
            s = 0.f;
#pragma unroll
            for (int c = 0; c < 7; c++) {
                if (a[c] * wbe == abe * we[c]) s += (float)c;
            }
        }
        float wsg = ws[g], bsg = bs[g];
        out[b * 25000 + g] = 1.f / (1.f + __expf(-(s * wsg + bsg)));
        out[19200000 + b * 25000 + g] = s;
    }
    __syncthreads();
    int tot4 = (nvalid * 7) >> 2;       // nvalid*7 divisible by 4 (256 or 168)
    float4* pib4 = (float4*)(out + 25600000u + (unsigned)(b * 25000 + g0) * 7u);
    const float4* spo4 = (const float4*)spo;
    for (int i = tid; i < tot4; i += 256) {
        pib4[i] = spo4[i];
    }
}

// ---------------------------------------------------------------------------
extern "C" void kernel_launch(void* const* d_in, const int* in_sizes, int n_in,
                              void* d_out, int out_size) {
    const float* z    = (const float*)d_in[0];
    const float* w0   = (const float*)d_in[1];
    const float* b0   = (const float*)d_in[2];
    const float* g0   = (const float*)d_in[3];
    const float* be0  = (const float*)d_in[4];
    const float* m0   = (const float*)d_in[5];
    const float* v0   = (const float*)d_in[6];
    const float* w1   = (const float*)d_in[7];
    const float* b1   = (const float*)d_in[8];
    const float* g1   = (const float*)d_in[9];
    const float* be1  = (const float*)d_in[10];
    const float* m1   = (const float*)d_in[11];
    const float* v1   = (const float*)d_in[12];
    const float* wr   = (const float*)d_in[13];
    const float* br   = (const float*)d_in[14];
    const float* wd   = (const float*)d_in[15];
    const float* bd   = (const float*)d_in[16];
    const float* wrho = (const float*)d_in[17];
    const float* brho = (const float*)d_in[18];
    const float* wsc  = (const float*)d_in[19];
    const float* bsc  = (const float*)d_in[20];
    float* out = (float*)d_out;

    // main stream: mlp -> rho_gemm -> sample ; side stream: tiled big_gemm
    mlp_kernel<<<256, 128>>>(z, w0, b0, g0, be0, m0, v0, w1, b1, g1, be1, m1, v1);
    cudaEventRecord(g_sx.e0, 0);
    cudaStreamWaitEvent(g_sx.s1, g_sx.e0, 0);
    big_gemm_kernel<<<dim3(98, 2, 2), 256, 0, g_sx.s1>>>(wr, br, wd, bd, out);
    rho_gemm_kernel<<<dim3(28, 16), 256>>>(wrho, brho);
    sample_kernel<<<dim3(98, 256), 256>>>(wsc, bsc, out);
    cudaEventRecord(g_sx.e1, g_sx.s1);
    cudaStreamWaitEvent(0, g_sx.e1, 0);
}